// round 1
// baseline (speedup 1.0000x reference)
#include <cuda_runtime.h>
#include <cuda_bf16.h>

// Problem constants
#define BB   32      // batch
#define NN   4096    // nodes
#define CIN  32
#define COUT 64
#define KDEG 5
#define PP   4
#define NNZ_ 65536
#define ROWW (CIN*BB)          // 1024 floats per node-row
#define ROWW4 (ROWW/4)         // 256 float4

// Scratch (device globals — allocation-free rule)
__device__ float g_xs[KDEG][NN*ROWW];     // Chebyshev terms, 5 x 16MB
__device__ int   g_count[NN];
__device__ int   g_rowptr[NN+1];
__device__ int   g_fill[NN];
__device__ int   g_ccol[NNZ_];
__device__ float g_cval[NNZ_];

// ---------------------------------------------------------------------------
// 1) transpose x[b][n][c] -> x0[n][c*32+b]
// ---------------------------------------------------------------------------
__global__ void k_transpose(const float* __restrict__ x) {
    __shared__ float t[32][33];
    int n = blockIdx.x;
    int tx = threadIdx.x;   // c on read, b on write
    int ty = threadIdx.y;   // b on read, c on write
    // read x[b=ty][n][c=tx] : contiguous over tx
    t[ty][tx] = x[(size_t)ty * (NN*CIN) + n*CIN + tx];
    __syncthreads();
    // write x0[n][c*32+b] with c=ty, b=tx : contiguous over tx
    g_xs[0][(size_t)n*ROWW + ty*32 + tx] = t[tx][ty];
}

// ---------------------------------------------------------------------------
// 2) CSR build (every launch; deterministic up to fp sum order ~1e-7)
// ---------------------------------------------------------------------------
__global__ void k_zero() {
    int i = blockIdx.x * blockDim.x + threadIdx.x;
    if (i < NN) g_count[i] = 0;
}

__global__ void k_count(const int* __restrict__ erow) {
    int i = blockIdx.x * blockDim.x + threadIdx.x;
    if (i < NNZ_) atomicAdd(&g_count[erow[i]], 1);
}

__global__ void k_scan() {   // 1 block, 1024 threads, 4 counts each
    __shared__ int s[1024];
    int t = threadIdx.x;
    int c0 = g_count[t*4+0], c1 = g_count[t*4+1],
        c2 = g_count[t*4+2], c3 = g_count[t*4+3];
    int sum = c0 + c1 + c2 + c3;
    s[t] = sum;
    __syncthreads();
    // Hillis-Steele inclusive scan
    for (int off = 1; off < 1024; off <<= 1) {
        int v = (t >= off) ? s[t-off] : 0;
        __syncthreads();
        s[t] += v;
        __syncthreads();
    }
    int base = (t > 0) ? s[t-1] : 0;
    int run = base;
    g_rowptr[t*4+0] = run; g_fill[t*4+0] = run; run += c0;
    g_rowptr[t*4+1] = run; g_fill[t*4+1] = run; run += c1;
    g_rowptr[t*4+2] = run; g_fill[t*4+2] = run; run += c2;
    g_rowptr[t*4+3] = run; g_fill[t*4+3] = run; run += c3;
    if (t == 1023) g_rowptr[NN] = run;
}

__global__ void k_scatter(const int* __restrict__ erow,
                          const int* __restrict__ ecol,
                          const float* __restrict__ eval) {
    int i = blockIdx.x * blockDim.x + threadIdx.x;
    if (i < NNZ_) {
        int r = erow[i];
        int pos = atomicAdd(&g_fill[r], 1);
        g_ccol[pos] = ecol[i];
        g_cval[pos] = eval[i];
    }
}

// ---------------------------------------------------------------------------
// 3) SPMM pass: x_k = (k==1) ? L x_0 : 2 L x_{k-1} - x_{k-2}
//    one block per output row, 256 threads, float4 per thread
// ---------------------------------------------------------------------------
__global__ void k_spmm(int k) {
    __shared__ int   sc[256];
    __shared__ float sv[256];
    int n = blockIdx.x;
    int t = threadIdx.x;
    int s = g_rowptr[n], e = g_rowptr[n+1];
    const float4* __restrict__ vin = reinterpret_cast<const float4*>(g_xs[k-1]);
    float4 acc = make_float4(0.f, 0.f, 0.f, 0.f);
    for (int base = s; base < e; base += 256) {
        int cnt = min(256, e - base);
        if (t < cnt) { sc[t] = g_ccol[base + t]; sv[t] = g_cval[base + t]; }
        __syncthreads();
        for (int i = 0; i < cnt; i++) {
            float v = sv[i];
            float4 xv = vin[(size_t)sc[i]*ROWW4 + t];
            acc.x = fmaf(v, xv.x, acc.x);
            acc.y = fmaf(v, xv.y, acc.y);
            acc.z = fmaf(v, xv.z, acc.z);
            acc.w = fmaf(v, xv.w, acc.w);
        }
        __syncthreads();
    }
    float4 r;
    if (k == 1) {
        r = acc;
    } else {
        const float4* vp = reinterpret_cast<const float4*>(g_xs[k-2]);
        float4 p = vp[(size_t)n*ROWW4 + t];
        r.x = 2.f*acc.x - p.x;
        r.y = 2.f*acc.y - p.y;
        r.z = 2.f*acc.z - p.z;
        r.w = 2.f*acc.w - p.w;
    }
    reinterpret_cast<float4*>(g_xs[k])[(size_t)n*ROWW4 + t] = r;
}

// ---------------------------------------------------------------------------
// 4) Fused GEMM + bias + ReLU + maxpool(P=4)
//    Block per node-group g (4 nodes). 128 threads.
//    Thread tile: 4 c_out x 4 b x 4 p.  smem: xs chunk [64][128] + w chunk [64][64]
//    y[b,n,o] = sum_{c,k} xs_k[n][c*32+b] * W[(c*5+k)*64 + o]
// ---------------------------------------------------------------------------
__global__ void __launch_bounds__(128) k_gemm(const float* __restrict__ W,
                                              const float* __restrict__ bias,
                                              float* __restrict__ out) {
    __shared__ float xsS[64][128];   // 32 KB  [f_local][p*32+b]
    __shared__ float wS[64][64];     // 16 KB  [f_local][c_out]
    int g  = blockIdx.x;             // 0..1023
    int n0 = g * PP;
    int t  = threadIdx.x;
    int cg = t & 15;                 // 16 c_out groups
    int bg = t >> 4;                 // 8 b groups
    int c0 = cg * 4, b0 = bg * 4;

    float acc[4][4][4];              // [p][bj][cj]
    #pragma unroll
    for (int p = 0; p < 4; p++)
        #pragma unroll
        for (int bj = 0; bj < 4; bj++)
            #pragma unroll
            for (int cj = 0; cj < 4; cj++) acc[p][bj][cj] = 0.f;

    for (int f0 = 0; f0 < KDEG*CIN; f0 += 64) {
        int fc = min(64, KDEG*CIN - f0);
        // stage xs chunk: fc*128 elements
        for (int e2 = t; e2 < fc*128; e2 += 128) {
            int lf = e2 >> 7;
            int r  = e2 & 127;
            int p  = r >> 5;
            int b  = r & 31;
            int f  = f0 + lf;
            int c  = f / KDEG;
            int k  = f - KDEG*c;
            xsS[lf][r] = g_xs[k][(size_t)(n0 + p)*ROWW + c*32 + b];
        }
        // stage weight chunk: fc*64 elements
        for (int e2 = t; e2 < fc*64; e2 += 128) {
            int lf = e2 >> 6;
            int cc = e2 & 63;
            wS[lf][cc] = W[(f0 + lf)*COUT + cc];
        }
        __syncthreads();
        #pragma unroll 4
        for (int i = 0; i < fc; i++) {
            float4 wv = *reinterpret_cast<const float4*>(&wS[i][c0]);
            #pragma unroll
            for (int p = 0; p < 4; p++) {
                float4 xv = *reinterpret_cast<const float4*>(&xsS[i][p*32 + b0]);
                acc[p][0][0] = fmaf(xv.x, wv.x, acc[p][0][0]);
                acc[p][0][1] = fmaf(xv.x, wv.y, acc[p][0][1]);
                acc[p][0][2] = fmaf(xv.x, wv.z, acc[p][0][2]);
                acc[p][0][3] = fmaf(xv.x, wv.w, acc[p][0][3]);
                acc[p][1][0] = fmaf(xv.y, wv.x, acc[p][1][0]);
                acc[p][1][1] = fmaf(xv.y, wv.y, acc[p][1][1]);
                acc[p][1][2] = fmaf(xv.y, wv.z, acc[p][1][2]);
                acc[p][1][3] = fmaf(xv.y, wv.w, acc[p][1][3]);
                acc[p][2][0] = fmaf(xv.z, wv.x, acc[p][2][0]);
                acc[p][2][1] = fmaf(xv.z, wv.y, acc[p][2][1]);
                acc[p][2][2] = fmaf(xv.z, wv.z, acc[p][2][2]);
                acc[p][2][3] = fmaf(xv.z, wv.w, acc[p][2][3]);
                acc[p][3][0] = fmaf(xv.w, wv.x, acc[p][3][0]);
                acc[p][3][1] = fmaf(xv.w, wv.y, acc[p][3][1]);
                acc[p][3][2] = fmaf(xv.w, wv.z, acc[p][3][2]);
                acc[p][3][3] = fmaf(xv.w, wv.w, acc[p][3][3]);
            }
        }
        __syncthreads();
    }

    // bias + relu + maxpool over p, write out[b][g][c_out]
    float4 bv = *reinterpret_cast<const float4*>(&bias[c0]);
    float bb[4] = {bv.x, bv.y, bv.z, bv.w};
    #pragma unroll
    for (int bj = 0; bj < 4; bj++) {
        #pragma unroll
        for (int cj = 0; cj < 4; cj++) {
            float m = 0.f;   // relu floor
            #pragma unroll
            for (int p = 0; p < 4; p++)
                m = fmaxf(m, acc[p][bj][cj] + bb[cj]);
            out[(size_t)(b0 + bj)*( (NN/PP)*COUT ) + (size_t)g*COUT + c0 + cj] = m;
        }
    }
}

// ---------------------------------------------------------------------------
extern "C" void kernel_launch(void* const* d_in, const int* in_sizes, int n_in,
                              void* d_out, int out_size) {
    const float* x        = (const float*)d_in[0];
    const float* edge_val = (const float*)d_in[1];
    const float* weight   = (const float*)d_in[2];
    const float* bias     = (const float*)d_in[3];
    const int*   edge_row = (const int*)d_in[4];
    const int*   edge_col = (const int*)d_in[5];
    float* out = (float*)d_out;

    k_transpose<<<NN, dim3(32, 32)>>>(x);
    k_zero<<<(NN + 255)/256, 256>>>();
    k_count<<<(NNZ_ + 255)/256, 256>>>(edge_row);
    k_scan<<<1, 1024>>>();
    k_scatter<<<(NNZ_ + 255)/256, 256>>>(edge_row, edge_col, edge_val);
    for (int k = 1; k < KDEG; k++)
        k_spmm<<<NN, 256>>>(k);
    k_gemm<<<NN/PP, 128>>>(weight, bias, out);
}

// round 2
// speedup vs baseline: 1.0654x; 1.0654x over previous
#include <cuda_runtime.h>
#include <cuda_fp16.h>

// Problem constants
#define BB   32
#define NN   4096
#define CIN  32
#define COUT 64
#define KDEG 5
#define PP   4
#define NNZ_ 65536
#define ROWW (CIN*BB)          // 1024 floats per node-row
#define ROWW4 (ROWW/4)         // 256 float4

// Scratch (device globals — allocation-free rule)
__device__ float  g_xs[KDEG][NN*ROWW];   // fp32 Chebyshev terms (GEMM + correction)
__device__ __half g_xh[KDEG][NN*ROWW];   // fp16 copies (gather source)
__device__ int    g_count[NN];
__device__ int    g_rowptr[NN+1];
__device__ int    g_fill[NN];
__device__ int    g_ccol[NNZ_];
__device__ float  g_cval[NNZ_];

// ---------------------------------------------------------------------------
// 1) transpose x[b][n][c] -> x0[n][c*32+b] (fp32 + fp16), zero g_count
// ---------------------------------------------------------------------------
__global__ void k_transpose(const float* __restrict__ x) {
    __shared__ float t[32][33];
    int n = blockIdx.x;
    int tx = threadIdx.x;   // c on read, b on write
    int ty = threadIdx.y;   // b on read, c on write
    if (tx == 0 && ty == 0) g_count[n] = 0;
    t[ty][tx] = x[(size_t)ty * (NN*CIN) + n*CIN + tx];
    __syncthreads();
    float v = t[tx][ty];
    size_t idx = (size_t)n*ROWW + ty*32 + tx;
    g_xs[0][idx] = v;
    g_xh[0][idx] = __float2half(v);
}

// ---------------------------------------------------------------------------
// 2) CSR build
// ---------------------------------------------------------------------------
__global__ void k_count(const int* __restrict__ erow) {
    int i = blockIdx.x * blockDim.x + threadIdx.x;
    if (i < NNZ_) atomicAdd(&g_count[erow[i]], 1);
}

__global__ void k_scan() {   // 1 block, 1024 threads, 4 counts each; warp-shuffle scan
    __shared__ int wsum[32];
    int t = threadIdx.x;
    int lane = t & 31, wid = t >> 5;
    int c0 = g_count[t*4+0], c1 = g_count[t*4+1],
        c2 = g_count[t*4+2], c3 = g_count[t*4+3];
    int sum = c0 + c1 + c2 + c3;
    int incl = sum;
    #pragma unroll
    for (int off = 1; off < 32; off <<= 1) {
        int v = __shfl_up_sync(0xffffffffu, incl, off);
        if (lane >= off) incl += v;
    }
    if (lane == 31) wsum[wid] = incl;
    __syncthreads();
    if (wid == 0) {
        int w = wsum[lane];
        int wi = w;
        #pragma unroll
        for (int off = 1; off < 32; off <<= 1) {
            int v = __shfl_up_sync(0xffffffffu, wi, off);
            if (lane >= off) wi += v;
        }
        wsum[lane] = wi - w;   // exclusive warp prefix
    }
    __syncthreads();
    int run = wsum[wid] + incl - sum;   // exclusive prefix for this thread
    g_rowptr[t*4+0] = run; g_fill[t*4+0] = run; run += c0;
    g_rowptr[t*4+1] = run; g_fill[t*4+1] = run; run += c1;
    g_rowptr[t*4+2] = run; g_fill[t*4+2] = run; run += c2;
    g_rowptr[t*4+3] = run; g_fill[t*4+3] = run; run += c3;
    if (t == 1023) g_rowptr[NN] = run;
}

__global__ void k_scatter(const int* __restrict__ erow,
                          const int* __restrict__ ecol,
                          const float* __restrict__ eval) {
    int i = blockIdx.x * blockDim.x + threadIdx.x;
    if (i < NNZ_) {
        int r = erow[i];
        int pos = atomicAdd(&g_fill[r], 1);
        g_ccol[pos] = ecol[i];
        g_cval[pos] = eval[i];
    }
}

// ---------------------------------------------------------------------------
// 3) SPMM pass: x_k = (k==1) ? L x_0 : 2 L x_{k-1} - x_{k-2}
//    Gather from fp16 copy, accumulate fp32, write both fp32 and fp16.
//    One block / row, 256 threads, 4 elements (8 bytes fp16) per thread.
// ---------------------------------------------------------------------------
__device__ __forceinline__ void acc_edge(float4& acc, float v, uint2 u) {
    __half2 a = *reinterpret_cast<__half2*>(&u.x);
    __half2 b = *reinterpret_cast<__half2*>(&u.y);
    float2 fa = __half22float2(a);
    float2 fb = __half22float2(b);
    acc.x = fmaf(v, fa.x, acc.x);
    acc.y = fmaf(v, fa.y, acc.y);
    acc.z = fmaf(v, fb.x, acc.z);
    acc.w = fmaf(v, fb.y, acc.w);
}

__global__ void __launch_bounds__(256) k_spmm(int k) {
    __shared__ int   sc[64];
    __shared__ float sv[64];
    int n = blockIdx.x;
    int t = threadIdx.x;
    int s = g_rowptr[n], e = g_rowptr[n+1];
    const __half* __restrict__ xin = g_xh[k-1];
    float4 acc = make_float4(0.f, 0.f, 0.f, 0.f);
    for (int base = s; base < e; base += 64) {
        int cnt = min(64, e - base);
        if (t < cnt) { sc[t] = g_ccol[base + t]; sv[t] = g_cval[base + t]; }
        __syncthreads();
        int i = 0;
        for (; i + 4 <= cnt; i += 4) {
            // 4 independent 8B loads for MLP
            uint2 u0 = *reinterpret_cast<const uint2*>(xin + (size_t)sc[i+0]*ROWW + t*4);
            uint2 u1 = *reinterpret_cast<const uint2*>(xin + (size_t)sc[i+1]*ROWW + t*4);
            uint2 u2 = *reinterpret_cast<const uint2*>(xin + (size_t)sc[i+2]*ROWW + t*4);
            uint2 u3 = *reinterpret_cast<const uint2*>(xin + (size_t)sc[i+3]*ROWW + t*4);
            acc_edge(acc, sv[i+0], u0);
            acc_edge(acc, sv[i+1], u1);
            acc_edge(acc, sv[i+2], u2);
            acc_edge(acc, sv[i+3], u3);
        }
        for (; i < cnt; i++) {
            uint2 u = *reinterpret_cast<const uint2*>(xin + (size_t)sc[i]*ROWW + t*4);
            acc_edge(acc, sv[i], u);
        }
        __syncthreads();
    }
    float4 r;
    if (k == 1) {
        r = acc;
    } else {
        const float4* vp = reinterpret_cast<const float4*>(g_xs[k-2]);
        float4 p = vp[(size_t)n*ROWW4 + t];
        r.x = 2.f*acc.x - p.x;
        r.y = 2.f*acc.y - p.y;
        r.z = 2.f*acc.z - p.z;
        r.w = 2.f*acc.w - p.w;
    }
    reinterpret_cast<float4*>(g_xs[k])[(size_t)n*ROWW4 + t] = r;
    __half2 h0 = __floats2half2_rn(r.x, r.y);
    __half2 h1 = __floats2half2_rn(r.z, r.w);
    uint2 hu;
    hu.x = *reinterpret_cast<unsigned*>(&h0);
    hu.y = *reinterpret_cast<unsigned*>(&h1);
    *reinterpret_cast<uint2*>(&g_xh[k][(size_t)n*ROWW + t*4]) = hu;
}

// ---------------------------------------------------------------------------
// 4) Fused GEMM + bias + ReLU + maxpool(P=4)  (fp32 inputs from g_xs)
// ---------------------------------------------------------------------------
__global__ void __launch_bounds__(128) k_gemm(const float* __restrict__ W,
                                              const float* __restrict__ bias,
                                              float* __restrict__ out) {
    __shared__ float xsS[64][128];   // [f_local][p*32+b]
    __shared__ float wS[64][64];     // [f_local][c_out]
    int g  = blockIdx.x;             // 0..1023
    int n0 = g * PP;
    int t  = threadIdx.x;
    int cg = t & 15;
    int bg = t >> 4;
    int c0 = cg * 4, b0 = bg * 4;

    float acc[4][4][4];              // [p][bj][cj]
    #pragma unroll
    for (int p = 0; p < 4; p++)
        #pragma unroll
        for (int bj = 0; bj < 4; bj++)
            #pragma unroll
            for (int cj = 0; cj < 4; cj++) acc[p][bj][cj] = 0.f;

    for (int f0 = 0; f0 < KDEG*CIN; f0 += 64) {
        int fc = min(64, KDEG*CIN - f0);
        for (int e2 = t; e2 < fc*128; e2 += 128) {
            int lf = e2 >> 7;
            int r  = e2 & 127;
            int p  = r >> 5;
            int b  = r & 31;
            int f  = f0 + lf;
            int c  = f / KDEG;
            int k  = f - KDEG*c;
            xsS[lf][r] = g_xs[k][(size_t)(n0 + p)*ROWW + c*32 + b];
        }
        for (int e2 = t; e2 < fc*64; e2 += 128) {
            int lf = e2 >> 6;
            int cc = e2 & 63;
            wS[lf][cc] = W[(f0 + lf)*COUT + cc];
        }
        __syncthreads();
        #pragma unroll 4
        for (int i = 0; i < fc; i++) {
            float4 wv = *reinterpret_cast<const float4*>(&wS[i][c0]);
            #pragma unroll
            for (int p = 0; p < 4; p++) {
                float4 xv = *reinterpret_cast<const float4*>(&xsS[i][p*32 + b0]);
                acc[p][0][0] = fmaf(xv.x, wv.x, acc[p][0][0]);
                acc[p][0][1] = fmaf(xv.x, wv.y, acc[p][0][1]);
                acc[p][0][2] = fmaf(xv.x, wv.z, acc[p][0][2]);
                acc[p][0][3] = fmaf(xv.x, wv.w, acc[p][0][3]);
                acc[p][1][0] = fmaf(xv.y, wv.x, acc[p][1][0]);
                acc[p][1][1] = fmaf(xv.y, wv.y, acc[p][1][1]);
                acc[p][1][2] = fmaf(xv.y, wv.z, acc[p][1][2]);
                acc[p][1][3] = fmaf(xv.y, wv.w, acc[p][1][3]);
                acc[p][2][0] = fmaf(xv.z, wv.x, acc[p][2][0]);
                acc[p][2][1] = fmaf(xv.z, wv.y, acc[p][2][1]);
                acc[p][2][2] = fmaf(xv.z, wv.z, acc[p][2][2]);
                acc[p][2][3] = fmaf(xv.z, wv.w, acc[p][2][3]);
                acc[p][3][0] = fmaf(xv.w, wv.x, acc[p][3][0]);
                acc[p][3][1] = fmaf(xv.w, wv.y, acc[p][3][1]);
                acc[p][3][2] = fmaf(xv.w, wv.z, acc[p][3][2]);
                acc[p][3][3] = fmaf(xv.w, wv.w, acc[p][3][3]);
            }
        }
        __syncthreads();
    }

    float4 bv = *reinterpret_cast<const float4*>(&bias[c0]);
    float bb[4] = {bv.x, bv.y, bv.z, bv.w};
    #pragma unroll
    for (int bj = 0; bj < 4; bj++) {
        #pragma unroll
        for (int cj = 0; cj < 4; cj++) {
            float m = 0.f;
            #pragma unroll
            for (int p = 0; p < 4; p++)
                m = fmaxf(m, acc[p][bj][cj] + bb[cj]);
            out[(size_t)(b0 + bj)*((NN/PP)*COUT) + (size_t)g*COUT + c0 + cj] = m;
        }
    }
}

// ---------------------------------------------------------------------------
extern "C" void kernel_launch(void* const* d_in, const int* in_sizes, int n_in,
                              void* d_out, int out_size) {
    const float* x        = (const float*)d_in[0];
    const float* edge_val = (const float*)d_in[1];
    const float* weight   = (const float*)d_in[2];
    const float* bias     = (const float*)d_in[3];
    const int*   edge_row = (const int*)d_in[4];
    const int*   edge_col = (const int*)d_in[5];
    float* out = (float*)d_out;

    k_transpose<<<NN, dim3(32, 32)>>>(x);
    k_count<<<(NNZ_ + 255)/256, 256>>>(edge_row);
    k_scan<<<1, 1024>>>();
    k_scatter<<<(NNZ_ + 255)/256, 256>>>(edge_row, edge_col, edge_val);
    for (int k = 1; k < KDEG; k++)
        k_spmm<<<NN, 256>>>(k);
    k_gemm<<<NN/PP, 128>>>(weight, bias, out);
}

// round 3
// speedup vs baseline: 2.1805x; 2.0465x over previous
#include <cuda_runtime.h>
#include <cuda_fp16.h>

// Problem constants
#define BB   32
#define NN   4096
#define CIN  32
#define COUT 64
#define KDEG 5
#define PP   4
#define NNZ_ 65536
#define ROWW (CIN*BB)          // 1024 elems per node-row
#define NF   (KDEG*CIN)        // 160 features

// Scratch (device globals — allocation-free rule)
__device__ __half g_xh[KDEG][NN*ROWW];   // fp16 Chebyshev terms
__device__ int    g_count[NN];
__device__ int    g_rowptr[NN+1];
__device__ int    g_fill[NN];
__device__ int    g_ccol[NNZ_];
__device__ float  g_cval[NNZ_];

// ---------------------------------------------------------------------------
// 1) transpose x[b][n][c] -> x0[n][c*32+b] (fp16), zero g_count
// ---------------------------------------------------------------------------
__global__ void k_transpose(const float* __restrict__ x) {
    __shared__ float t[32][33];
    int n = blockIdx.x;
    int tx = threadIdx.x;
    int ty = threadIdx.y;
    if (tx == 0 && ty == 0) g_count[n] = 0;
    t[ty][tx] = x[(size_t)ty * (NN*CIN) + n*CIN + tx];
    __syncthreads();
    g_xh[0][(size_t)n*ROWW + ty*32 + tx] = __float2half(t[tx][ty]);
}

// ---------------------------------------------------------------------------
// 2) CSR build
// ---------------------------------------------------------------------------
__global__ void k_count(const int* __restrict__ erow) {
    int i = blockIdx.x * blockDim.x + threadIdx.x;
    if (i < NNZ_) atomicAdd(&g_count[erow[i]], 1);
}

__global__ void k_scan() {   // 1 block, 1024 threads, 4 counts each
    __shared__ int wsum[32];
    int t = threadIdx.x;
    int lane = t & 31, wid = t >> 5;
    int c0 = g_count[t*4+0], c1 = g_count[t*4+1],
        c2 = g_count[t*4+2], c3 = g_count[t*4+3];
    int sum = c0 + c1 + c2 + c3;
    int incl = sum;
    #pragma unroll
    for (int off = 1; off < 32; off <<= 1) {
        int v = __shfl_up_sync(0xffffffffu, incl, off);
        if (lane >= off) incl += v;
    }
    if (lane == 31) wsum[wid] = incl;
    __syncthreads();
    if (wid == 0) {
        int w = wsum[lane];
        int wi = w;
        #pragma unroll
        for (int off = 1; off < 32; off <<= 1) {
            int v = __shfl_up_sync(0xffffffffu, wi, off);
            if (lane >= off) wi += v;
        }
        wsum[lane] = wi - w;
    }
    __syncthreads();
    int run = wsum[wid] + incl - sum;
    g_rowptr[t*4+0] = run; g_fill[t*4+0] = run; run += c0;
    g_rowptr[t*4+1] = run; g_fill[t*4+1] = run; run += c1;
    g_rowptr[t*4+2] = run; g_fill[t*4+2] = run; run += c2;
    g_rowptr[t*4+3] = run; g_fill[t*4+3] = run; run += c3;
    if (t == 1023) g_rowptr[NN] = run;
}

__global__ void k_scatter(const int* __restrict__ erow,
                          const int* __restrict__ ecol,
                          const float* __restrict__ eval) {
    int i = blockIdx.x * blockDim.x + threadIdx.x;
    if (i < NNZ_) {
        int r = erow[i];
        int pos = atomicAdd(&g_fill[r], 1);
        g_ccol[pos] = ecol[i];
        g_cval[pos] = eval[i];
    }
}

// ---------------------------------------------------------------------------
// 3) SPMM pass: x_k = (k==1) ? L x_0 : 2 L x_{k-1} - x_{k-2}  (all fp16 storage)
// ---------------------------------------------------------------------------
__device__ __forceinline__ void acc_edge(float4& acc, float v, uint2 u) {
    float2 fa = __half22float2(*reinterpret_cast<__half2*>(&u.x));
    float2 fb = __half22float2(*reinterpret_cast<__half2*>(&u.y));
    acc.x = fmaf(v, fa.x, acc.x);
    acc.y = fmaf(v, fa.y, acc.y);
    acc.z = fmaf(v, fb.x, acc.z);
    acc.w = fmaf(v, fb.y, acc.w);
}

__global__ void __launch_bounds__(256) k_spmm(int k) {
    __shared__ int   sc[64];
    __shared__ float sv[64];
    int n = blockIdx.x;
    int t = threadIdx.x;
    int s = g_rowptr[n], e = g_rowptr[n+1];
    const __half* __restrict__ xin = g_xh[k-1];
    float4 acc = make_float4(0.f, 0.f, 0.f, 0.f);
    for (int base = s; base < e; base += 64) {
        int cnt = min(64, e - base);
        if (t < cnt) { sc[t] = g_ccol[base + t]; sv[t] = g_cval[base + t]; }
        __syncthreads();
        int i = 0;
        for (; i + 4 <= cnt; i += 4) {
            uint2 u0 = *reinterpret_cast<const uint2*>(xin + (size_t)sc[i+0]*ROWW + t*4);
            uint2 u1 = *reinterpret_cast<const uint2*>(xin + (size_t)sc[i+1]*ROWW + t*4);
            uint2 u2 = *reinterpret_cast<const uint2*>(xin + (size_t)sc[i+2]*ROWW + t*4);
            uint2 u3 = *reinterpret_cast<const uint2*>(xin + (size_t)sc[i+3]*ROWW + t*4);
            acc_edge(acc, sv[i+0], u0);
            acc_edge(acc, sv[i+1], u1);
            acc_edge(acc, sv[i+2], u2);
            acc_edge(acc, sv[i+3], u3);
        }
        for (; i < cnt; i++) {
            uint2 u = *reinterpret_cast<const uint2*>(xin + (size_t)sc[i]*ROWW + t*4);
            acc_edge(acc, sv[i], u);
        }
        __syncthreads();
    }
    float4 r = acc;
    if (k > 1) {
        uint2 pu = *reinterpret_cast<const uint2*>(&g_xh[k-2][(size_t)n*ROWW + t*4]);
        float2 pa = __half22float2(*reinterpret_cast<__half2*>(&pu.x));
        float2 pb = __half22float2(*reinterpret_cast<__half2*>(&pu.y));
        r.x = 2.f*acc.x - pa.x;
        r.y = 2.f*acc.y - pa.y;
        r.z = 2.f*acc.z - pb.x;
        r.w = 2.f*acc.w - pb.y;
    }
    __half2 h0 = __floats2half2_rn(r.x, r.y);
    __half2 h1 = __floats2half2_rn(r.z, r.w);
    uint2 hu;
    hu.x = *reinterpret_cast<unsigned*>(&h0);
    hu.y = *reinterpret_cast<unsigned*>(&h1);
    *reinterpret_cast<uint2*>(&g_xh[k][(size_t)n*ROWW + t*4]) = hu;
}

// ---------------------------------------------------------------------------
// 4) Tensor-core GEMM + bias + ReLU + maxpool(P=4)
//    Block = 1 pool group: M=128 rows (4 nodes x 32 b), N=64, K=160.
//    aS: f-major fp16 [80][136], double pass over K. wS: [160][72] fp16.
//    4 warps: warp w owns node p=w (rows w*32..w*32+31). Pool via smem.
// ---------------------------------------------------------------------------
#define A_STRIDE 136   // halves; 272B = 17*16 (16B-aligned rows, conflict-free)
#define W_STRIDE 72    // halves; 144B = 9*16

__device__ __forceinline__ void ldsm_x4_trans(unsigned& r0, unsigned& r1,
                                              unsigned& r2, unsigned& r3,
                                              unsigned addr) {
    asm volatile("ldmatrix.sync.aligned.m8n8.x4.trans.shared.b16 {%0,%1,%2,%3}, [%4];\n"
                 : "=r"(r0), "=r"(r1), "=r"(r2), "=r"(r3) : "r"(addr));
}

__device__ __forceinline__ void mma16816(float* d, unsigned a0, unsigned a1,
                                         unsigned a2, unsigned a3,
                                         unsigned b0, unsigned b1) {
    asm volatile("mma.sync.aligned.m16n8k16.row.col.f32.f16.f16.f32 "
                 "{%0,%1,%2,%3}, {%4,%5,%6,%7}, {%8,%9}, {%0,%1,%2,%3};\n"
                 : "+f"(d[0]), "+f"(d[1]), "+f"(d[2]), "+f"(d[3])
                 : "r"(a0), "r"(a1), "r"(a2), "r"(a3), "r"(b0), "r"(b1));
}

__global__ void __launch_bounds__(128) k_gemm(const float* __restrict__ W,
                                              const float* __restrict__ bias,
                                              float* __restrict__ out) {
    __shared__ __align__(16) char buf[80*A_STRIDE*2 + NF*W_STRIDE*2]; // 44800 B
    __half* aS = reinterpret_cast<__half*>(buf);                       // [80][A_STRIDE]
    __half* wS = reinterpret_cast<__half*>(buf + 80*A_STRIDE*2);       // [160][W_STRIDE]
    float*  red = reinterpret_cast<float*>(buf);                       // [4][32][64] after sync

    int g  = blockIdx.x;          // 0..1023
    int n0 = g * PP;
    int t  = threadIdx.x;
    int w  = t >> 5;              // warp = node p
    int lane = t & 31;

    unsigned aS_base = (unsigned)__cvta_generic_to_shared(aS);
    unsigned wS_base = (unsigned)__cvta_generic_to_shared(wS);

    float acc[2][8][4];           // [mt][nt][d]
    #pragma unroll
    for (int mt = 0; mt < 2; mt++)
        #pragma unroll
        for (int nt = 0; nt < 8; nt++)
            #pragma unroll
            for (int d = 0; d < 4; d++) acc[mt][nt][d] = 0.f;

    // stage W (fp32 -> fp16), once: 160*64 elems, float4 chunks
    #pragma unroll
    for (int it = 0; it < 20; it++) {
        int ch = it*128 + t;             // 0..2559
        int f  = ch >> 4;
        int o4 = (ch & 15) * 4;
        float4 wv = *reinterpret_cast<const float4*>(W + f*COUT + o4);
        __half2 h0 = __floats2half2_rn(wv.x, wv.y);
        __half2 h1 = __floats2half2_rn(wv.z, wv.w);
        uint2 hu;
        hu.x = *reinterpret_cast<unsigned*>(&h0);
        hu.y = *reinterpret_cast<unsigned*>(&h1);
        *reinterpret_cast<uint2*>(wS + f*W_STRIDE + o4) = hu;
    }

    for (int f0 = 0; f0 < NF; f0 += 80) {
        // stage A slice: 80 features x 128 rows, f-major (aS[lf][row])
        #pragma unroll
        for (int it = 0; it < 10; it++) {
            int ch = it*128 + t;         // 0..1279
            int lf = ch >> 4;
            int rc = ch & 15;
            int p  = rc >> 2;
            int b0 = (rc & 3) * 8;
            int f  = f0 + lf;
            int c  = f / KDEG;
            int k  = f - KDEG*c;
            uint4 v = *reinterpret_cast<const uint4*>(
                &g_xh[k][(size_t)(n0 + p)*ROWW + c*32 + b0]);
            *reinterpret_cast<uint4*>(aS + lf*A_STRIDE + p*32 + b0) = v;
        }
        __syncthreads();

        #pragma unroll
        for (int kc = 0; kc < 5; kc++) {
            int lf0 = kc * 16;
            int fg  = f0 + lf0;
            int grp = lane >> 3, lrow = lane & 7;
            // A fragment addresses (stored col-major [f][row], trans load)
            int a_f = lf0 + ((grp == 2 || grp == 3) ? 8 : 0) + lrow;
            int a_c = ((grp == 1 || grp == 3) ? 8 : 0);
            unsigned a0r, a1r, a2r, a3r, a4r, a5r, a6r, a7r;
            {
                unsigned addr0 = aS_base + (a_f*A_STRIDE + w*32 + 0*16 + a_c) * 2;
                ldsm_x4_trans(a0r, a1r, a2r, a3r, addr0);
                unsigned addr1 = aS_base + (a_f*A_STRIDE + w*32 + 1*16 + a_c) * 2;
                ldsm_x4_trans(a4r, a5r, a6r, a7r, addr1);
            }
            // B: 4 x ldmatrix.x4 covering n-tile pairs
            int b_f = fg + ((grp == 1 || grp == 3) ? 8 : 0) + lrow;
            int b_n = ((grp == 2 || grp == 3) ? 8 : 0);
            #pragma unroll
            for (int ntp = 0; ntp < 4; ntp++) {
                unsigned b0r, b1r, b2r, b3r;
                unsigned addr = wS_base + (b_f*W_STRIDE + ntp*16 + b_n) * 2;
                ldsm_x4_trans(b0r, b1r, b2r, b3r, addr);
                mma16816(acc[0][ntp*2+0], a0r, a1r, a2r, a3r, b0r, b1r);
                mma16816(acc[0][ntp*2+1], a0r, a1r, a2r, a3r, b2r, b3r);
                mma16816(acc[1][ntp*2+0], a4r, a5r, a6r, a7r, b0r, b1r);
                mma16816(acc[1][ntp*2+1], a4r, a5r, a6r, a7r, b2r, b3r);
            }
        }
        __syncthreads();
    }

    // write accumulators to red[p][row32][64]
    #pragma unroll
    for (int mt = 0; mt < 2; mt++) {
        int r1 = mt*16 + (lane >> 2);
        #pragma unroll
        for (int nt = 0; nt < 8; nt++) {
            int c = nt*8 + (lane & 3)*2;
            red[(w*32 + r1)*64 + c]     = acc[mt][nt][0];
            red[(w*32 + r1)*64 + c + 1] = acc[mt][nt][1];
            red[(w*32 + r1 + 8)*64 + c]     = acc[mt][nt][2];
            red[(w*32 + r1 + 8)*64 + c + 1] = acc[mt][nt][3];
        }
    }
    __syncthreads();

    // bias + relu + maxpool across p, write out[b][g][o]
    #pragma unroll
    for (int it = 0; it < 16; it++) {
        int idx = it*128 + t;        // 0..2047
        int b = idx >> 6;
        int o = idx & 63;
        float bo = bias[o];
        float m = 0.f;               // relu floor
        #pragma unroll
        for (int p = 0; p < 4; p++)
            m = fmaxf(m, red[(p*32 + b)*64 + o] + bo);
        out[(size_t)b*((NN/PP)*COUT) + (size_t)g*COUT + o] = m;
    }
}

// ---------------------------------------------------------------------------
extern "C" void kernel_launch(void* const* d_in, const int* in_sizes, int n_in,
                              void* d_out, int out_size) {
    const float* x        = (const float*)d_in[0];
    const float* edge_val = (const float*)d_in[1];
    const float* weight   = (const float*)d_in[2];
    const float* bias     = (const float*)d_in[3];
    const int*   edge_row = (const int*)d_in[4];
    const int*   edge_col = (const int*)d_in[5];
    float* out = (float*)d_out;

    k_transpose<<<NN, dim3(32, 32)>>>(x);
    k_count<<<(NNZ_ + 255)/256, 256>>>(edge_row);
    k_scan<<<1, 1024>>>();
    k_scatter<<<(NNZ_ + 255)/256, 256>>>(edge_row, edge_col, edge_val);
    for (int k = 1; k < KDEG; k++)
        k_spmm<<<NN, 256>>>(k);
    k_gemm<<<NN/PP, 128>>>(weight, bias, out);
}